// round 12
// baseline (speedup 1.0000x reference)
#include <cuda_runtime.h>
#include <cuda_bf16.h>
#include <cstddef>

// Sorted segment-sum: feat[1e6, 128] fp32 -> out[4096, 128] fp32.
// Winning architecture (R10): static dispatch, 2368 blocks = 4 waves of 4
// resident blocks/SM, one warp per contiguous chain of 8-row tiles, guided
// two-tier split (7/8 of tiles to the first 3 waves, 1/8 to the last wave
// whose completion spread is the only exposed tail). R12: SINGLE-KERNEL -
// the output zero-init is folded into segsum. First 64 blocks zero 1/64 of
// the 2MB output each (overlapped with streaming), then bump a MONOTONIC
// g_zero_done counter. Warps gate their FIRST flush (naturally ~5-7us in)
// on g_zero_done >= (epoch+1)*64, where epoch = g_launch_ctr / GRID_BLOCKS
// is replay-consistent because graph replays serialize. No resets needed.
// Hot loop: 8 rows/iter, branch-free front-batched streaming loads
// (2x int4 seg + 8x float4 feat => MLP ~10/warp). Sortedness: last id in
// batch == cur => whole batch == cur. Flushes are atomicAdds into the 2MB
// L2-resident output.

#define WARPS_PER_BLOCK 8
#define THREADS (WARPS_PER_BLOCK * 32)
#define GRID_BLOCKS 2368                        // 4 waves x 592
#define N_CHAINS ((long)GRID_BLOCKS * WARPS_PER_BLOCK)  // 18944
#define T1_CHAINS 14208                         // first 3 waves
#define T2_CHAINS 4736                          // last wave
#define ZB 64                                   // zeroing blocks
#define D_FEAT 128

__device__ unsigned int g_launch_ctr;   // monotonic, never reset
__device__ unsigned int g_zero_done;    // monotonic, never reset

__device__ __forceinline__ float4 f4add(float4 a, float4 b) {
    return make_float4(a.x + b.x, a.y + b.y, a.z + b.z, a.w + b.w);
}

__device__ __forceinline__ void wait_zero(unsigned int target, bool& ready) {
    if (!ready) {
        while (*(volatile unsigned int*)&g_zero_done < target) { }
        __threadfence();
        ready = true;
    }
}

__device__ __forceinline__ void flush_acc(float* __restrict__ out, int cur,
                                          int lane, float4 acc,
                                          unsigned int target, bool& ready) {
    wait_zero(target, ready);
    float* dst = out + (size_t)cur * D_FEAT + lane * 4;
    atomicAdd(dst + 0, acc.x);
    atomicAdd(dst + 1, acc.y);
    atomicAdd(dst + 2, acc.z);
    atomicAdd(dst + 3, acc.w);
}

__global__ __launch_bounds__(THREADS, 4)
void segsum_kernel(const float4* __restrict__ feat4,
                   const int* __restrict__ seg,
                   float* __restrict__ out,
                   int n_rows, int n4) {
    __shared__ unsigned int s_epoch;
    if (threadIdx.x == 0) {
        unsigned int v = atomicAdd(&g_launch_ctr, 1u);
        s_epoch = v / GRID_BLOCKS;   // replay index (replays serialize)
    }
    __syncthreads();
    const unsigned int target = (s_epoch + 1u) * ZB;

    // First ZB blocks zero the output, then signal.
    if (blockIdx.x < ZB) {
        float4* o4 = reinterpret_cast<float4*>(out);
        const int per_blk = n4 / ZB;             // 2048
        int base = blockIdx.x * per_blk + threadIdx.x;
        const float4 z = make_float4(0.f, 0.f, 0.f, 0.f);
        for (int i = 0; i < per_blk; i += THREADS)
            o4[base + i] = z;
        __threadfence();
        if (threadIdx.x == 0) atomicAdd(&g_zero_done, 1u);
    }

    const int warp = threadIdx.x >> 5;
    const int lane = threadIdx.x & 31;
    const long chain = (long)blockIdx.x * WARPS_PER_BLOCK + warp;

    const long n_tiles = n_rows >> 3;            // full 8-row tiles
    const long tiles_t1 = (n_tiles * 7) >> 3;    // 7/8 to the first 3 waves

    // Guided two-tier balanced split.
    long t0, t1;
    if (chain < T1_CHAINS) {
        t0 = (chain * tiles_t1) / T1_CHAINS;
        t1 = ((chain + 1) * tiles_t1) / T1_CHAINS;
    } else {
        const long c2 = chain - T1_CHAINS;
        const long tiles_t2 = n_tiles - tiles_t1;
        t0 = tiles_t1 + (c2 * tiles_t2) / T2_CHAINS;
        t1 = tiles_t1 + ((c2 + 1) * tiles_t2) / T2_CHAINS;
    }
    long r0 = t0 << 3;
    long r1 = t1 << 3;
    if (chain == N_CHAINS - 1) r1 = n_rows;      // remainder rows
    if (r0 >= r1) return;

    bool ready = false;
    float4 acc = make_float4(0.f, 0.f, 0.f, 0.f);
    int cur = __ldcs(seg + r0);

    long r = r0;
    // ---------- hot loop: branch-free loads, 8 rows / iter ----------
    for (; r + 8 <= r1; r += 8) {
        const int4 sA = __ldcs(reinterpret_cast<const int4*>(seg + r));
        const int4 sB = __ldcs(reinterpret_cast<const int4*>(seg + r + 4));
        const float4* base = feat4 + (size_t)r * (D_FEAT / 4) + lane;
        const float4 v0 = __ldcs(base + 0 * 32);
        const float4 v1 = __ldcs(base + 1 * 32);
        const float4 v2 = __ldcs(base + 2 * 32);
        const float4 v3 = __ldcs(base + 3 * 32);
        const float4 v4 = __ldcs(base + 4 * 32);
        const float4 v5 = __ldcs(base + 5 * 32);
        const float4 v6 = __ldcs(base + 6 * 32);
        const float4 v7 = __ldcs(base + 7 * 32);

        if (sB.w == cur) {
            // sorted ids: last == cur  =>  all 8 == cur
            float4 t0s = f4add(f4add(v0, v1), f4add(v2, v3));
            float4 t1s = f4add(f4add(v4, v5), f4add(v6, v7));
            acc = f4add(acc, f4add(t0s, t1s));
        } else {
            // cold path: segment boundary inside this batch
            int s[8] = {sA.x, sA.y, sA.z, sA.w, sB.x, sB.y, sB.z, sB.w};
            float4 v[8] = {v0, v1, v2, v3, v4, v5, v6, v7};
            #pragma unroll
            for (int i = 0; i < 8; i++) {
                if (s[i] != cur) {
                    flush_acc(out, cur, lane, acc, target, ready);
                    acc = make_float4(0.f, 0.f, 0.f, 0.f);
                    cur = s[i];
                }
                acc = f4add(acc, v[i]);
            }
        }
    }
    // ---------- scalar tail (only last chain, if n_rows % 8 != 0) ----------
    for (; r < r1; ++r) {
        int s = __ldcs(seg + r);
        float4 v = __ldcs(feat4 + (size_t)r * (D_FEAT / 4) + lane);
        if (s != cur) {
            flush_acc(out, cur, lane, acc, target, ready);
            acc = make_float4(0.f, 0.f, 0.f, 0.f);
            cur = s;
        }
        acc = f4add(acc, v);
    }

    flush_acc(out, cur, lane, acc, target, ready);
}

extern "C" void kernel_launch(void* const* d_in, const int* in_sizes, int n_in,
                              void* d_out, int out_size) {
    const float* feat = (const float*)d_in[0];
    const int* seg = (const int*)d_in[1];
    float* out = (float*)d_out;

    const int n_rows = in_sizes[0] / D_FEAT;  // 1,000,000
    const int n4 = out_size / 4;              // 131072

    segsum_kernel<<<GRID_BLOCKS, THREADS>>>((const float4*)feat, seg, out,
                                            n_rows, n4);
}